// round 9
// baseline (speedup 1.0000x reference)
#include <cuda_runtime.h>
#include <cuda_bf16.h>
#include <cstdint>
#include <cstddef>

#define D_MODEL 1024
#define D_SAE   8192
#define N_MAX   16384
#define KTOP    32
#define NCAND   256
#define CTHRESH 40

// ---------------------------------------------------------------------------
// static device scratch (no runtime allocation)
// ---------------------------------------------------------------------------
static __device__ __nv_bfloat16 g_ah[(size_t)N_MAX * D_MODEL];   // 32 MB  bf16(x - b_dec)
static __device__ __nv_bfloat16 g_wh[(size_t)D_SAE * D_MODEL];   // 16 MB  bf16(W_enc)
static __device__ float g_wdt[(size_t)D_SAE * D_MODEL];          // 32 MB  W_dec^T
static __device__ int   g_cand[(size_t)N_MAX * NCAND];           // 16 MB
static __device__ int   g_nc[N_MAX];
static __device__ int   g_tidx[N_MAX * KTOP];
static __device__ float g_tval[N_MAX * KTOP];
static __device__ float g_mse[N_MAX];
static __device__ float g_l0[N_MAX];

// ---------------------------------------------------------------------------
// helpers
// ---------------------------------------------------------------------------
__device__ __forceinline__ uint32_t s2u(const void* p) {
    uint32_t a;
    asm("{ .reg .u64 t; cvta.to.shared.u64 t, %1; cvt.u32.u64 %0, t; }"
        : "=r"(a) : "l"(p));
    return a;
}
__device__ __forceinline__ void cpa16(uint32_t s, const void* g) {
    asm volatile("cp.async.cg.shared.global [%0], [%1], 16;"
                 :: "r"(s), "l"(g));
}
__device__ __forceinline__ uint32_t pack2(float a, float b) {
    __nv_bfloat162 h = __floats2bfloat162_rn(a, b);
    return *reinterpret_cast<uint32_t*>(&h);
}
__device__ __forceinline__ void ldsm4(uint32_t* r, uint32_t addr) {
    asm volatile("ldmatrix.sync.aligned.m8n8.x4.shared.b16 {%0,%1,%2,%3}, [%4];"
                 : "=r"(r[0]), "=r"(r[1]), "=r"(r[2]), "=r"(r[3]) : "r"(addr));
}
__device__ __forceinline__ void mma16816(float* c, const uint32_t* a,
                                         const uint32_t* b) {
    asm volatile(
        "mma.sync.aligned.m16n8k16.row.col.f32.bf16.bf16.f32 "
        "{%0,%1,%2,%3}, {%4,%5,%6,%7}, {%8,%9}, {%0,%1,%2,%3};"
        : "+f"(c[0]), "+f"(c[1]), "+f"(c[2]), "+f"(c[3])
        : "r"(a[0]), "r"(a[1]), "r"(a[2]), "r"(a[3]), "r"(b[0]), "r"(b[1]));
}
// monotonic orderable key for float
__device__ __forceinline__ uint32_t fkey(float v) {
    uint32_t u = __float_as_uint(v);
    return (u & 0x80000000u) ? ~u : (u | 0x80000000u);
}

// ---------------------------------------------------------------------------
// Kernel A: bf16(x - b_dec)
// ---------------------------------------------------------------------------
__global__ __launch_bounds__(256) void convert_x_kernel(
    const float* __restrict__ x, const float* __restrict__ bdec)
{
    const size_t i = ((size_t)blockIdx.x * 256 + threadIdx.x) * 4;
    float4 v = *(const float4*)(x + i);
    const float4 bd = *(const float4*)(bdec + (i & (D_MODEL - 1)));
    uint2 h;
    h.x = pack2(v.x - bd.x, v.y - bd.y);
    h.y = pack2(v.z - bd.z, v.w - bd.w);
    *(uint2*)(g_ah + i) = h;
}

// Kernel B: bf16(W_enc)
__global__ __launch_bounds__(256) void convert_w_kernel(const float* __restrict__ w)
{
    const size_t i = ((size_t)blockIdx.x * 256 + threadIdx.x) * 4;
    float4 v = *(const float4*)(w + i);
    uint2 h;
    h.x = pack2(v.x, v.y);
    h.y = pack2(v.z, v.w);
    *(uint2*)(g_wh + i) = h;
}

// ---------------------------------------------------------------------------
// Kernel C: approximate encode GEMM via mma.sync bf16 (fp32 accum)
// pre[m][n] ~= (x-bdec)[m]·Wenc[n] + benc[n]
// BM=BN=128, BK=32, 8 warps (4x2), warp tile 32x64, double-buffered cp.async.
// 80-byte smem row stride -> conflict-free ldmatrix.
// ---------------------------------------------------------------------------
#define TILE_B   10240            // 128 rows * 80 bytes
#define OFF_A    0
#define OFF_B    (TILE_B)
#define STAGE_B  (2 * TILE_B)     // 20480
#define GEMM_SMEM (2 * STAGE_B)   // 40960

__global__ __launch_bounds__(256, 2) void enc_gemm_mma(
    const float* __restrict__ benc, float* __restrict__ pre)
{
    extern __shared__ char smbuf[];
    const uint32_t sb = s2u(smbuf);
    const int tid = threadIdx.x, wid = tid >> 5, lane = tid & 31;
    const size_t bm = (size_t)blockIdx.y * 128;
    const size_t bn = (size_t)blockIdx.x * 128;
    const int warpM = (wid & 3) * 32;
    const int warpN = (wid >> 2) * 64;

    const char* gA = (const char*)g_ah + bm * 2048;
    const char* gB = (const char*)g_wh + bn * 2048;

    const int q0r = tid >> 2, q0c = tid & 3;
    const int q1r = (tid + 256) >> 2, q1c = tid & 3;
    const uint32_t so0 = q0r * 80 + q0c * 16;
    const uint32_t so1 = q1r * 80 + q1c * 16;

    auto load_stage = [&](int s, int buf) {
        const uint32_t base = sb + buf * STAGE_B;
        const size_t go0 = (size_t)q0r * 2048 + (size_t)s * 64 + q0c * 16;
        const size_t go1 = (size_t)q1r * 2048 + (size_t)s * 64 + q1c * 16;
        cpa16(base + OFF_A + so0, gA + go0);
        cpa16(base + OFF_A + so1, gA + go1);
        cpa16(base + OFF_B + so0, gB + go0);
        cpa16(base + OFF_B + so1, gB + go1);
    };

    float acc[2][8][4];
    #pragma unroll
    for (int i = 0; i < 2; i++)
        #pragma unroll
        for (int j = 0; j < 8; j++)
            #pragma unroll
            for (int k = 0; k < 4; k++) acc[i][j][k] = 0.f;

    const uint32_t aBase =
        (uint32_t)(warpM + (lane & 15)) * 80 + (uint32_t)(lane >> 4) * 16;
    const uint32_t bBase =
        (uint32_t)(warpN + (lane & 7) + ((lane >> 4) & 1) * 8) * 80 +
        (uint32_t)((lane >> 3) & 1) * 16;

    load_stage(0, 0);
    asm volatile("cp.async.commit_group;" ::: "memory");
    load_stage(1, 1);
    asm volatile("cp.async.commit_group;" ::: "memory");

    #pragma unroll 1
    for (int s = 0; s < 32; s++) {
        asm volatile("cp.async.wait_group 1;" ::: "memory");
        __syncthreads();
        const uint32_t base = sb + (s & 1) * STAGE_B;

        #pragma unroll
        for (int ks = 0; ks < 2; ks++) {
            const uint32_t kso = ks * 32;
            uint32_t a0[4], a1[4], bb[4][4];
            ldsm4(a0, base + OFF_A + aBase + kso);
            ldsm4(a1, base + OFF_A + aBase + 1280 + kso);
            #pragma unroll
            for (int nt = 0; nt < 4; nt++)
                ldsm4(bb[nt], base + OFF_B + bBase + nt * 1280 + kso);
            #pragma unroll
            for (int ni = 0; ni < 8; ni++) {
                const uint32_t* bf = &bb[ni >> 1][(ni & 1) * 2];
                mma16816(acc[0][ni], a0, bf);
                mma16816(acc[1][ni], a1, bf);
            }
        }
        __syncthreads();
        if (s + 2 < 32) {
            load_stage(s + 2, s & 1);
            asm volatile("cp.async.commit_group;" ::: "memory");
        }
    }

    // epilogue: + b_enc, write approx pre
    const int gr = lane >> 2;
    const int cp = (lane & 3) * 2;
    #pragma unroll
    for (int mi = 0; mi < 2; mi++) {
        #pragma unroll
        for (int j = 0; j < 2; j++) {
            const size_t row = bm + warpM + mi * 16 + gr + j * 8;
            float* prow = pre + row * D_SAE + bn + warpN;
            const float* be = benc + bn + warpN;
            #pragma unroll
            for (int ni = 0; ni < 8; ni++) {
                const int col = ni * 8 + cp;
                float2 o;
                o.x = acc[mi][ni][j * 2 + 0] + __ldg(be + col);
                o.y = acc[mi][ni][j * 2 + 1] + __ldg(be + col + 1);
                *(float2*)(prow + col) = o;
            }
        }
    }
}

// ---------------------------------------------------------------------------
// Kernel D: W_dec transpose
// ---------------------------------------------------------------------------
__global__ void transpose_wdec_kernel(const float* __restrict__ Wdec)
{
    __shared__ float t[32][33];
    const int bx = blockIdx.x * 32;   // d_sae
    const int by = blockIdx.y * 32;   // d_model
    const int tx = threadIdx.x, ty = threadIdx.y;   // (32, 8)
    #pragma unroll
    for (int i = 0; i < 32; i += 8)
        t[ty + i][tx] = Wdec[(size_t)(by + ty + i) * D_SAE + bx + tx];
    __syncthreads();
    #pragma unroll
    for (int i = 0; i < 32; i += 8)
        g_wdt[(size_t)(bx + ty + i) * D_MODEL + by + tx] = t[tx][ty + i];
}

// ---------------------------------------------------------------------------
// Kernel E: per-row candidate select via 2048-bucket histogram.
// Emits all elements with approx value >= the CTHRESH-th largest (cap NCAND
// is structurally unreachable for this distribution), then zeroes feat row.
// ---------------------------------------------------------------------------
__global__ __launch_bounds__(256) void cand_kernel(float* __restrict__ feat)
{
    __shared__ float srow[D_SAE];
    __shared__ unsigned hist[2048];
    __shared__ unsigned csum[256];
    __shared__ int sT;
    __shared__ int scnt;

    const int row = blockIdx.x, tid = threadIdx.x;
    float* f = feat + (size_t)row * D_SAE;

    #pragma unroll
    for (int j = 0; j < 8; j++) hist[tid + j * 256] = 0;
    if (tid == 0) scnt = 0;
    __syncthreads();

    for (int i = tid; i < D_SAE / 4; i += 256) {
        float4 v = *(const float4*)&f[i * 4];
        *(float4*)&srow[i * 4] = v;
        atomicAdd(&hist[fkey(v.x) >> 21], 1u);
        atomicAdd(&hist[fkey(v.y) >> 21], 1u);
        atomicAdd(&hist[fkey(v.z) >> 21], 1u);
        atomicAdd(&hist[fkey(v.w) >> 21], 1u);
    }
    __syncthreads();

    // chunk sums (8 buckets/thread) + inclusive suffix scan
    unsigned cs = 0;
    #pragma unroll
    for (int j = 0; j < 8; j++) cs += hist[tid * 8 + j];
    csum[tid] = cs;
    __syncthreads();
    for (int off = 1; off < 256; off <<= 1) {
        unsigned add = (tid + off < 256) ? csum[tid + off] : 0;
        __syncthreads();
        csum[tid] += add;
        __syncthreads();
    }
    // owner of the crossing chunk finds the highest bucket with cum >= CTHRESH
    {
        const unsigned here = csum[tid];
        const unsigned next = (tid < 255) ? csum[tid + 1] : 0;
        if (here >= CTHRESH && next < CTHRESH) {
            unsigned running = next;
            int T = tid * 8;
            for (int b = tid * 8 + 7; b >= tid * 8; b--) {
                running += hist[b];
                if (running >= CTHRESH) { T = b; break; }
            }
            sT = T;
        }
    }
    __syncthreads();
    const int T = sT;

    // compact candidate indices to global scratch
    for (int i = tid; i < D_SAE; i += 256) {
        if ((int)(fkey(srow[i]) >> 21) >= T) {
            int p = atomicAdd(&scnt, 1);
            if (p < NCAND) g_cand[(size_t)row * NCAND + p] = i;
        }
    }
    __syncthreads();
    if (tid == 0) g_nc[row] = scnt < NCAND ? scnt : NCAND;

    // zero feature row (fixup kernel scatters afterwards)
    const float4 z = {0.f, 0.f, 0.f, 0.f};
    for (int i = tid; i < D_SAE / 4; i += 256)
        *(float4*)&f[i * 4] = z;
}

// ---------------------------------------------------------------------------
// Kernel F: exact fp32 recompute of candidates, exact top-32, scatter.
// ---------------------------------------------------------------------------
__global__ __launch_bounds__(256) void fixup_kernel(
    const float* __restrict__ x, const float* __restrict__ Wenc,
    const float* __restrict__ benc, const float* __restrict__ bdec,
    float* __restrict__ feat)
{
    __shared__ float xs[D_MODEL];
    __shared__ float cv[NCAND];
    __shared__ int   ci[NCAND];
    __shared__ float kv[KTOP];
    __shared__ int   kidx[KTOP];

    const int row = blockIdx.x, tid = threadIdx.x;
    const int wid = tid >> 5, lane = tid & 31;
    const int nc = g_nc[row];

    for (int i = tid; i < D_MODEL; i += 256)
        xs[i] = x[(size_t)row * D_MODEL + i] - bdec[i];
    if (tid < nc) ci[tid] = g_cand[(size_t)row * NCAND + tid];
    __syncthreads();

    // exact fp32 dot per candidate (one warp per candidate, round-robin)
    for (int c = wid; c < nc; c += 8) {
        const float* wr = Wenc + (size_t)ci[c] * D_MODEL;
        float acc = 0.f;
        #pragma unroll
        for (int j = 0; j < 8; j++) {
            const int o = (j * 32 + lane) * 4;
            const float4 w = *(const float4*)(wr + o);
            const float4 a = *(const float4*)(xs + o);
            acc += a.x * w.x + a.y * w.y + a.z * w.z + a.w * w.w;
        }
        #pragma unroll
        for (int o = 16; o; o >>= 1)
            acc += __shfl_xor_sync(0xffffffffu, acc, o);
        if (lane == 0) cv[c] = acc + __ldg(benc + ci[c]);
    }
    __syncthreads();

    // warp 0: exact top-32 (value desc, tie -> lower feature index)
    if (wid == 0) {
        for (int t = 0; t < KTOP; t++) {
            float bv = -3.4e38f; int bi = 0x7fffffff, bs = -1;
            for (int s = lane; s < nc; s += 32) {
                const float v = cv[s]; const int idx = ci[s];
                if (v > bv || (v == bv && idx < bi)) { bv = v; bi = idx; bs = s; }
            }
            #pragma unroll
            for (int o = 16; o; o >>= 1) {
                const float ov = __shfl_xor_sync(0xffffffffu, bv, o);
                const int   oi = __shfl_xor_sync(0xffffffffu, bi, o);
                const int   os = __shfl_xor_sync(0xffffffffu, bs, o);
                if (ov > bv || (ov == bv && oi < bi)) { bv = ov; bi = oi; bs = os; }
            }
            if (lane == 0) {
                kv[t] = bv; kidx[t] = bi;
                if (bs >= 0) cv[bs] = -3.4e38f;
            }
            __syncwarp();
        }
        if (lane < KTOP) {
            const int idx = kidx[lane];
            float v = kv[lane]; if (v < 0.f) v = 0.f;
            g_tval[row * KTOP + lane] = v;
            g_tidx[row * KTOP + lane] = idx;
            if (idx != 0x7fffffff)
                feat[(size_t)row * D_SAE + idx] = v;
        }
    }
}

// ---------------------------------------------------------------------------
// Kernel G: sparse decode + per-row partials
// ---------------------------------------------------------------------------
__global__ __launch_bounds__(256) void decode_kernel(
    const float* __restrict__ x, const float* __restrict__ bdec,
    float* __restrict__ xhat)
{
    __shared__ int   si[KTOP];
    __shared__ float sv[KTOP];
    __shared__ float red[256];

    const int row = blockIdx.x, tid = threadIdx.x;
    if (tid < KTOP) {
        si[tid] = g_tidx[row * KTOP + tid];
        sv[tid] = g_tval[row * KTOP + tid];
    }
    __syncthreads();

    float4 acc = *(const float4*)&bdec[tid * 4];
    #pragma unroll 8
    for (int k = 0; k < KTOP; k++) {
        const float v = sv[k];
        const float4 w = *(const float4*)&g_wdt[(size_t)si[k] * D_MODEL + tid * 4];
        acc.x += v * w.x; acc.y += v * w.y; acc.z += v * w.z; acc.w += v * w.w;
    }
    *(float4*)&xhat[(size_t)row * D_MODEL + tid * 4] = acc;

    const float4 xv = *(const float4*)&x[(size_t)row * D_MODEL + tid * 4];
    const float dx = acc.x - xv.x, dy = acc.y - xv.y,
                dz = acc.z - xv.z, dw = acc.w - xv.w;
    red[tid] = dx * dx + dy * dy + dz * dz + dw * dw;
    __syncthreads();
    for (int s = 128; s > 0; s >>= 1) {
        if (tid < s) red[tid] += red[tid + s];
        __syncthreads();
    }
    if (tid == 0) {
        g_mse[row] = red[0];
        int c = 0;
        #pragma unroll
        for (int k = 0; k < KTOP; k++) c += (sv[k] > 0.f);
        g_l0[row] = (float)c;
    }
}

// ---------------------------------------------------------------------------
// Kernel H: final scalars
// ---------------------------------------------------------------------------
__global__ __launch_bounds__(256) void finalize_kernel(
    float* __restrict__ scal, int N, float inv_elems)
{
    __shared__ float r1[256], r2[256];
    const int tid = threadIdx.x;
    float s1 = 0.f, s2 = 0.f;
    for (int i = tid; i < N; i += 256) { s1 += g_mse[i]; s2 += g_l0[i]; }
    r1[tid] = s1; r2[tid] = s2;
    __syncthreads();
    for (int s = 128; s > 0; s >>= 1) {
        if (tid < s) { r1[tid] += r1[tid + s]; r2[tid] += r2[tid + s]; }
        __syncthreads();
    }
    if (tid == 0) {
        const float mse = r1[0] * inv_elems;
        scal[0] = mse;  scal[1] = mse;  scal[2] = 0.f;
        scal[3] = r2[0] / (float)N;
    }
}

// ---------------------------------------------------------------------------
// launch
// ---------------------------------------------------------------------------
extern "C" void kernel_launch(void* const* d_in, const int* in_sizes, int n_in,
                              void* d_out, int out_size)
{
    const float* x    = (const float*)d_in[0];
    const float* Wenc = (const float*)d_in[1];
    const float* benc = (const float*)d_in[2];
    const float* Wdec = (const float*)d_in[3];
    const float* bdec = (const float*)d_in[4];

    const int d_model = in_sizes[4];            // 1024
    const int N       = in_sizes[0] / d_model;  // 16384
    (void)n_in; (void)out_size;

    float* out  = (float*)d_out;
    float* xhat = out;                                   // [N, d_model]
    float* feat = out + (size_t)N * d_model;             // [N, d_sae]
    float* scal = feat + (size_t)N * D_SAE;              // 4 scalars

    // 1. bf16 conversions
    convert_x_kernel<<<(N * D_MODEL) / 1024, 256>>>(x, bdec);
    convert_w_kernel<<<(D_SAE * D_MODEL) / 1024, 256>>>(Wenc);

    // 2. W_dec transpose
    transpose_wdec_kernel<<<dim3(D_SAE / 32, D_MODEL / 32), dim3(32, 8)>>>(Wdec);

    // 3. approximate encode GEMM (bf16 tensor cores) -> feat region
    dim3 gg(D_SAE / 128, N / 128);
    enc_gemm_mma<<<gg, 256, GEMM_SMEM>>>(benc, feat);

    // 4. per-row candidate selection + zero feat
    cand_kernel<<<N, 256>>>(feat);

    // 5. exact fp32 fixup: recompute candidates, exact top-32, scatter
    fixup_kernel<<<N, 256>>>(x, Wenc, benc, bdec, feat);

    // 6. sparse decode + per-row partials
    decode_kernel<<<N, 256>>>(x, bdec, xhat);

    // 7. scalars
    finalize_kernel<<<1, 256>>>(scal, N, 1.0f / ((float)N * (float)d_model));
}

// round 10
// speedup vs baseline: 1.1013x; 1.1013x over previous
#include <cuda_runtime.h>
#include <cuda_bf16.h>
#include <cstdint>
#include <cstddef>

#define D_MODEL 1024
#define D_SAE   8192
#define N_MAX   16384
#define KTOP    32
#define NCAND   256
#define CTHRESH 40
#define SUBT    56

// ---------------------------------------------------------------------------
// static device scratch (no runtime allocation)
// ---------------------------------------------------------------------------
static __device__ __nv_bfloat16 g_ah[(size_t)N_MAX * D_MODEL];   // 32 MB  bf16(x - b_dec)
static __device__ __nv_bfloat16 g_wh[(size_t)D_SAE * D_MODEL];   // 16 MB  bf16(W_enc)
static __device__ float g_wdt[(size_t)D_SAE * D_MODEL];          // 32 MB  W_dec^T
static __device__ int   g_cand[(size_t)N_MAX * NCAND];           // 16 MB
static __device__ int   g_nc[N_MAX];
static __device__ int   g_tidx[N_MAX * KTOP];
static __device__ float g_tval[N_MAX * KTOP];
static __device__ float g_mse[N_MAX];
static __device__ float g_l0[N_MAX];

// ---------------------------------------------------------------------------
// helpers
// ---------------------------------------------------------------------------
__device__ __forceinline__ uint32_t s2u(const void* p) {
    uint32_t a;
    asm("{ .reg .u64 t; cvta.to.shared.u64 t, %1; cvt.u32.u64 %0, t; }"
        : "=r"(a) : "l"(p));
    return a;
}
__device__ __forceinline__ void cpa16(uint32_t s, const void* g) {
    asm volatile("cp.async.cg.shared.global [%0], [%1], 16;"
                 :: "r"(s), "l"(g));
}
__device__ __forceinline__ uint32_t pack2(float a, float b) {
    __nv_bfloat162 h = __floats2bfloat162_rn(a, b);
    return *reinterpret_cast<uint32_t*>(&h);
}
__device__ __forceinline__ void ldsm4(uint32_t* r, uint32_t addr) {
    asm volatile("ldmatrix.sync.aligned.m8n8.x4.shared.b16 {%0,%1,%2,%3}, [%4];"
                 : "=r"(r[0]), "=r"(r[1]), "=r"(r[2]), "=r"(r[3]) : "r"(addr));
}
__device__ __forceinline__ void mma16816(float* c, const uint32_t* a,
                                         const uint32_t* b) {
    asm volatile(
        "mma.sync.aligned.m16n8k16.row.col.f32.bf16.bf16.f32 "
        "{%0,%1,%2,%3}, {%4,%5,%6,%7}, {%8,%9}, {%0,%1,%2,%3};"
        : "+f"(c[0]), "+f"(c[1]), "+f"(c[2]), "+f"(c[3])
        : "r"(a[0]), "r"(a[1]), "r"(a[2]), "r"(a[3]), "r"(b[0]), "r"(b[1]));
}
// monotonic orderable key for float
__device__ __forceinline__ uint32_t fkey(float v) {
    uint32_t u = __float_as_uint(v);
    return (u & 0x80000000u) ? ~u : (u | 0x80000000u);
}

// ---------------------------------------------------------------------------
// Kernel A: bf16(x - b_dec)
// ---------------------------------------------------------------------------
__global__ __launch_bounds__(256) void convert_x_kernel(
    const float* __restrict__ x, const float* __restrict__ bdec)
{
    const size_t i = ((size_t)blockIdx.x * 256 + threadIdx.x) * 4;
    float4 v = *(const float4*)(x + i);
    const float4 bd = *(const float4*)(bdec + (i & (D_MODEL - 1)));
    uint2 h;
    h.x = pack2(v.x - bd.x, v.y - bd.y);
    h.y = pack2(v.z - bd.z, v.w - bd.w);
    *(uint2*)(g_ah + i) = h;
}

// Kernel B: bf16(W_enc)
__global__ __launch_bounds__(256) void convert_w_kernel(const float* __restrict__ w)
{
    const size_t i = ((size_t)blockIdx.x * 256 + threadIdx.x) * 4;
    float4 v = *(const float4*)(w + i);
    uint2 h;
    h.x = pack2(v.x, v.y);
    h.y = pack2(v.z, v.w);
    *(uint2*)(g_wh + i) = h;
}

// ---------------------------------------------------------------------------
// Kernel C: approximate encode GEMM via mma.sync bf16 (fp32 accum)
// BM=BN=128, BK=32, 8 warps (4x2), warp tile 32x64, 3-stage cp.async
// pipeline with ONE __syncthreads per K-stage.
// 80-byte smem row stride -> conflict-free ldmatrix.
// ---------------------------------------------------------------------------
#define TILE_B   10240            // 128 rows * 80 bytes
#define OFF_A    0
#define OFF_B    (TILE_B)
#define STAGE_B  (2 * TILE_B)     // 20480
#define NSTAGE   3
#define GEMM_SMEM (NSTAGE * STAGE_B)   // 61440

__global__ __launch_bounds__(256, 2) void enc_gemm_mma(
    const float* __restrict__ benc, float* __restrict__ pre)
{
    extern __shared__ char smbuf[];
    const uint32_t sb = s2u(smbuf);
    const int tid = threadIdx.x, wid = tid >> 5, lane = tid & 31;
    const size_t bm = (size_t)blockIdx.y * 128;
    const size_t bn = (size_t)blockIdx.x * 128;
    const int warpM = (wid & 3) * 32;
    const int warpN = (wid >> 2) * 64;

    const char* gA = (const char*)g_ah + bm * 2048;
    const char* gB = (const char*)g_wh + bn * 2048;

    const int q0r = tid >> 2, q0c = tid & 3;
    const int q1r = (tid + 256) >> 2, q1c = tid & 3;
    const uint32_t so0 = q0r * 80 + q0c * 16;
    const uint32_t so1 = q1r * 80 + q1c * 16;

    auto load_stage = [&](int s, int buf) {
        const uint32_t base = sb + buf * STAGE_B;
        const size_t go0 = (size_t)q0r * 2048 + (size_t)s * 64 + q0c * 16;
        const size_t go1 = (size_t)q1r * 2048 + (size_t)s * 64 + q1c * 16;
        cpa16(base + OFF_A + so0, gA + go0);
        cpa16(base + OFF_A + so1, gA + go1);
        cpa16(base + OFF_B + so0, gB + go0);
        cpa16(base + OFF_B + so1, gB + go1);
    };

    float acc[2][8][4];
    #pragma unroll
    for (int i = 0; i < 2; i++)
        #pragma unroll
        for (int j = 0; j < 8; j++)
            #pragma unroll
            for (int k = 0; k < 4; k++) acc[i][j][k] = 0.f;

    const uint32_t aBase =
        (uint32_t)(warpM + (lane & 15)) * 80 + (uint32_t)(lane >> 4) * 16;
    const uint32_t bBase =
        (uint32_t)(warpN + (lane & 7) + ((lane >> 4) & 1) * 8) * 80 +
        (uint32_t)((lane >> 3) & 1) * 16;

    // prologue: stages 0,1 into buffers 0,1
    load_stage(0, 0);
    asm volatile("cp.async.commit_group;" ::: "memory");
    load_stage(1, 1);
    asm volatile("cp.async.commit_group;" ::: "memory");

    int buf = 0;
    #pragma unroll 1
    for (int s = 0; s < 32; s++) {
        // stage s resident once <=1 group pending (only s+1 outstanding)
        asm volatile("cp.async.wait_group 1;" ::: "memory");
        __syncthreads();   // also guarantees compute of s-1 fully done ->
                           // its buffer is reusable for stage s+2 below
        if (s + 2 < 32) {
            int nb = buf + 2; if (nb >= NSTAGE) nb -= NSTAGE;
            load_stage(s + 2, nb);
            asm volatile("cp.async.commit_group;" ::: "memory");
        } else {
            // keep group counting consistent: commit empty group
            asm volatile("cp.async.commit_group;" ::: "memory");
        }

        const uint32_t base = sb + buf * STAGE_B;
        #pragma unroll
        for (int ks = 0; ks < 2; ks++) {
            const uint32_t kso = ks * 32;
            uint32_t a0[4], a1[4], bb[4][4];
            ldsm4(a0, base + OFF_A + aBase + kso);
            ldsm4(a1, base + OFF_A + aBase + 1280 + kso);
            #pragma unroll
            for (int nt = 0; nt < 4; nt++)
                ldsm4(bb[nt], base + OFF_B + bBase + nt * 1280 + kso);
            #pragma unroll
            for (int ni = 0; ni < 8; ni++) {
                const uint32_t* bf = &bb[ni >> 1][(ni & 1) * 2];
                mma16816(acc[0][ni], a0, bf);
                mma16816(acc[1][ni], a1, bf);
            }
        }
        buf++; if (buf >= NSTAGE) buf = 0;
    }

    // epilogue: + b_enc, write approx pre
    const int gr = lane >> 2;
    const int cp = (lane & 3) * 2;
    #pragma unroll
    for (int mi = 0; mi < 2; mi++) {
        #pragma unroll
        for (int j = 0; j < 2; j++) {
            const size_t row = bm + warpM + mi * 16 + gr + j * 8;
            float* prow = pre + row * D_SAE + bn + warpN;
            const float* be = benc + bn + warpN;
            #pragma unroll
            for (int ni = 0; ni < 8; ni++) {
                const int col = ni * 8 + cp;
                float2 o;
                o.x = acc[mi][ni][j * 2 + 0] + __ldg(be + col);
                o.y = acc[mi][ni][j * 2 + 1] + __ldg(be + col + 1);
                *(float2*)(prow + col) = o;
            }
        }
    }
}

// ---------------------------------------------------------------------------
// Kernel D: W_dec transpose
// ---------------------------------------------------------------------------
__global__ void transpose_wdec_kernel(const float* __restrict__ Wdec)
{
    __shared__ float t[32][33];
    const int bx = blockIdx.x * 32;   // d_sae
    const int by = blockIdx.y * 32;   // d_model
    const int tx = threadIdx.x, ty = threadIdx.y;   // (32, 8)
    #pragma unroll
    for (int i = 0; i < 32; i += 8)
        t[ty + i][tx] = Wdec[(size_t)(by + ty + i) * D_SAE + bx + tx];
    __syncthreads();
    #pragma unroll
    for (int i = 0; i < 32; i += 8)
        g_wdt[(size_t)(bx + ty + i) * D_MODEL + by + tx] = t[tx][ty + i];
}

// ---------------------------------------------------------------------------
// Kernel E: per-row candidate select: coarse 2048-bucket histogram, then
// 64-way sub-bucket refinement inside the threshold bucket so the emitted
// candidate count lands near SUBT (instead of ~136). Then zero feat row.
// ---------------------------------------------------------------------------
__global__ __launch_bounds__(256) void cand_kernel(float* __restrict__ feat)
{
    __shared__ float srow[D_SAE];
    __shared__ unsigned hist[2048];
    __shared__ unsigned csum[256];
    __shared__ unsigned subh[64];
    __shared__ int sT, sTs;
    __shared__ unsigned sAbove;
    __shared__ int scnt;

    const int row = blockIdx.x, tid = threadIdx.x;
    float* f = feat + (size_t)row * D_SAE;

    #pragma unroll
    for (int j = 0; j < 8; j++) hist[tid + j * 256] = 0;
    if (tid < 64) subh[tid] = 0;
    if (tid == 0) scnt = 0;
    __syncthreads();

    for (int i = tid; i < D_SAE / 4; i += 256) {
        float4 v = *(const float4*)&f[i * 4];
        *(float4*)&srow[i * 4] = v;
        atomicAdd(&hist[fkey(v.x) >> 21], 1u);
        atomicAdd(&hist[fkey(v.y) >> 21], 1u);
        atomicAdd(&hist[fkey(v.z) >> 21], 1u);
        atomicAdd(&hist[fkey(v.w) >> 21], 1u);
    }
    __syncthreads();

    // chunk sums (8 buckets/thread) + inclusive suffix scan
    unsigned cs = 0;
    #pragma unroll
    for (int j = 0; j < 8; j++) cs += hist[tid * 8 + j];
    csum[tid] = cs;
    __syncthreads();
    for (int off = 1; off < 256; off <<= 1) {
        unsigned add = (tid + off < 256) ? csum[tid + off] : 0;
        __syncthreads();
        csum[tid] += add;
        __syncthreads();
    }
    // owner of the crossing chunk finds the highest bucket with cum >= CTHRESH
    {
        const unsigned here = csum[tid];
        const unsigned next = (tid < 255) ? csum[tid + 1] : 0;
        if (here >= CTHRESH && next < CTHRESH) {
            unsigned running = next;
            int T = tid * 8;
            for (int b = tid * 8 + 7; b >= tid * 8; b--) {
                running += hist[b];
                if (running >= CTHRESH) { T = b; break; }
            }
            sT = T;
            // count strictly above bucket T
            unsigned abv = next;
            for (int b = tid * 8 + 7; b > T; b--) abv += hist[b];
            sAbove = abv;
        }
    }
    __syncthreads();
    const int T = sT;
    const unsigned above = sAbove;

    // sub-histogram of bucket T members (6 more key bits -> 64 sub-buckets)
    for (int i = tid; i < D_SAE; i += 256) {
        const uint32_t k = fkey(srow[i]);
        if ((int)(k >> 21) == T)
            atomicAdd(&subh[(k >> 15) & 63u], 1u);
    }
    __syncthreads();
    if (tid == 0) {
        unsigned run = above;
        int Ts = 0;
        for (int b = 63; b >= 0; b--) {
            run += subh[b];
            if (run >= SUBT) { Ts = b; break; }
        }
        sTs = Ts;
    }
    __syncthreads();
    const int Ts = sTs;

    // compact candidate indices to global scratch
    for (int i = tid; i < D_SAE; i += 256) {
        const uint32_t k = fkey(srow[i]);
        const int b = (int)(k >> 21);
        if (b > T || (b == T && (int)((k >> 15) & 63u) >= Ts)) {
            int p = atomicAdd(&scnt, 1);
            if (p < NCAND) g_cand[(size_t)row * NCAND + p] = i;
        }
    }
    __syncthreads();
    if (tid == 0) g_nc[row] = scnt < NCAND ? scnt : NCAND;

    // zero feature row (fixup kernel scatters afterwards)
    const float4 z = {0.f, 0.f, 0.f, 0.f};
    for (int i = tid; i < D_SAE / 4; i += 256)
        *(float4*)&f[i * 4] = z;
}

// ---------------------------------------------------------------------------
// Kernel F: exact fp32 recompute of candidates, exact top-32, scatter.
// ---------------------------------------------------------------------------
__global__ __launch_bounds__(256) void fixup_kernel(
    const float* __restrict__ x, const float* __restrict__ Wenc,
    const float* __restrict__ benc, const float* __restrict__ bdec,
    float* __restrict__ feat)
{
    __shared__ float xs[D_MODEL];
    __shared__ float cv[NCAND];
    __shared__ int   ci[NCAND];
    __shared__ float kv[KTOP];
    __shared__ int   kidx[KTOP];

    const int row = blockIdx.x, tid = threadIdx.x;
    const int wid = tid >> 5, lane = tid & 31;
    const int nc = g_nc[row];

    for (int i = tid; i < D_MODEL; i += 256)
        xs[i] = x[(size_t)row * D_MODEL + i] - bdec[i];
    if (tid < nc) ci[tid] = g_cand[(size_t)row * NCAND + tid];
    __syncthreads();

    // exact fp32 dot per candidate (one warp per candidate, round-robin)
    for (int c = wid; c < nc; c += 8) {
        const float* wr = Wenc + (size_t)ci[c] * D_MODEL;
        float acc = 0.f;
        #pragma unroll
        for (int j = 0; j < 8; j++) {
            const int o = (j * 32 + lane) * 4;
            const float4 w = *(const float4*)(wr + o);
            const float4 a = *(const float4*)(xs + o);
            acc += a.x * w.x + a.y * w.y + a.z * w.z + a.w * w.w;
        }
        #pragma unroll
        for (int o = 16; o; o >>= 1)
            acc += __shfl_xor_sync(0xffffffffu, acc, o);
        if (lane == 0) cv[c] = acc + __ldg(benc + ci[c]);
    }
    __syncthreads();

    // warp 0: exact top-32 (value desc, tie -> lower feature index)
    if (wid == 0) {
        for (int t = 0; t < KTOP; t++) {
            float bv = -3.4e38f; int bi = 0x7fffffff, bs = -1;
            for (int s = lane; s < nc; s += 32) {
                const float v = cv[s]; const int idx = ci[s];
                if (v > bv || (v == bv && idx < bi)) { bv = v; bi = idx; bs = s; }
            }
            #pragma unroll
            for (int o = 16; o; o >>= 1) {
                const float ov = __shfl_xor_sync(0xffffffffu, bv, o);
                const int   oi = __shfl_xor_sync(0xffffffffu, bi, o);
                const int   os = __shfl_xor_sync(0xffffffffu, bs, o);
                if (ov > bv || (ov == bv && oi < bi)) { bv = ov; bi = oi; bs = os; }
            }
            if (lane == 0) {
                kv[t] = bv; kidx[t] = bi;
                if (bs >= 0) cv[bs] = -3.4e38f;
            }
            __syncwarp();
        }
        if (lane < KTOP) {
            const int idx = kidx[lane];
            float v = kv[lane]; if (v < 0.f) v = 0.f;
            g_tval[row * KTOP + lane] = v;
            g_tidx[row * KTOP + lane] = idx;
            if (idx != 0x7fffffff)
                feat[(size_t)row * D_SAE + idx] = v;
        }
    }
}

// ---------------------------------------------------------------------------
// Kernel G: sparse decode + per-row partials
// ---------------------------------------------------------------------------
__global__ __launch_bounds__(256) void decode_kernel(
    const float* __restrict__ x, const float* __restrict__ bdec,
    float* __restrict__ xhat)
{
    __shared__ int   si[KTOP];
    __shared__ float sv[KTOP];
    __shared__ float red[256];

    const int row = blockIdx.x, tid = threadIdx.x;
    if (tid < KTOP) {
        si[tid] = g_tidx[row * KTOP + tid];
        sv[tid] = g_tval[row * KTOP + tid];
    }
    __syncthreads();

    float4 acc = *(const float4*)&bdec[tid * 4];
    #pragma unroll 8
    for (int k = 0; k < KTOP; k++) {
        const float v = sv[k];
        const float4 w = *(const float4*)&g_wdt[(size_t)si[k] * D_MODEL + tid * 4];
        acc.x += v * w.x; acc.y += v * w.y; acc.z += v * w.z; acc.w += v * w.w;
    }
    *(float4*)&xhat[(size_t)row * D_MODEL + tid * 4] = acc;

    const float4 xv = *(const float4*)&x[(size_t)row * D_MODEL + tid * 4];
    const float dx = acc.x - xv.x, dy = acc.y - xv.y,
                dz = acc.z - xv.z, dw = acc.w - xv.w;
    red[tid] = dx * dx + dy * dy + dz * dz + dw * dw;
    __syncthreads();
    for (int s = 128; s > 0; s >>= 1) {
        if (tid < s) red[tid] += red[tid + s];
        __syncthreads();
    }
    if (tid == 0) {
        g_mse[row] = red[0];
        int c = 0;
        #pragma unroll
        for (int k = 0; k < KTOP; k++) c += (sv[k] > 0.f);
        g_l0[row] = (float)c;
    }
}

// ---------------------------------------------------------------------------
// Kernel H: final scalars
// ---------------------------------------------------------------------------
__global__ __launch_bounds__(256) void finalize_kernel(
    float* __restrict__ scal, int N, float inv_elems)
{
    __shared__ float r1[256], r2[256];
    const int tid = threadIdx.x;
    float s1 = 0.f, s2 = 0.f;
    for (int i = tid; i < N; i += 256) { s1 += g_mse[i]; s2 += g_l0[i]; }
    r1[tid] = s1; r2[tid] = s2;
    __syncthreads();
    for (int s = 128; s > 0; s >>= 1) {
        if (tid < s) { r1[tid] += r1[tid + s]; r2[tid] += r2[tid + s]; }
        __syncthreads();
    }
    if (tid == 0) {
        const float mse = r1[0] * inv_elems;
        scal[0] = mse;  scal[1] = mse;  scal[2] = 0.f;
        scal[3] = r2[0] / (float)N;
    }
}

// ---------------------------------------------------------------------------
// launch
// ---------------------------------------------------------------------------
extern "C" void kernel_launch(void* const* d_in, const int* in_sizes, int n_in,
                              void* d_out, int out_size)
{
    const float* x    = (const float*)d_in[0];
    const float* Wenc = (const float*)d_in[1];
    const float* benc = (const float*)d_in[2];
    const float* Wdec = (const float*)d_in[3];
    const float* bdec = (const float*)d_in[4];

    const int d_model = in_sizes[4];            // 1024
    const int N       = in_sizes[0] / d_model;  // 16384
    (void)n_in; (void)out_size;

    float* out  = (float*)d_out;
    float* xhat = out;                                   // [N, d_model]
    float* feat = out + (size_t)N * d_model;             // [N, d_sae]
    float* scal = feat + (size_t)N * D_SAE;              // 4 scalars

    // 60 KB dynamic smem for the 3-stage GEMM (idempotent, capture-safe)
    cudaFuncSetAttribute(enc_gemm_mma,
                         cudaFuncAttributeMaxDynamicSharedMemorySize, GEMM_SMEM);

    // 1. bf16 conversions
    convert_x_kernel<<<(N * D_MODEL) / 1024, 256>>>(x, bdec);
    convert_w_kernel<<<(D_SAE * D_MODEL) / 1024, 256>>>(Wenc);

    // 2. W_dec transpose
    transpose_wdec_kernel<<<dim3(D_SAE / 32, D_MODEL / 32), dim3(32, 8)>>>(Wdec);

    // 3. approximate encode GEMM (bf16 tensor cores) -> feat region
    dim3 gg(D_SAE / 128, N / 128);
    enc_gemm_mma<<<gg, 256, GEMM_SMEM>>>(benc, feat);

    // 4. per-row candidate selection (sub-bucket refined) + zero feat
    cand_kernel<<<N, 256>>>(feat);

    // 5. exact fp32 fixup: recompute candidates, exact top-32, scatter
    fixup_kernel<<<N, 256>>>(x, Wenc, benc, bdec, feat);

    // 6. sparse decode + per-row partials
    decode_kernel<<<N, 256>>>(x, bdec, xhat);

    // 7. scalars
    finalize_kernel<<<1, 256>>>(scal, N, 1.0f / ((float)N * (float)d_model));
}

// round 11
// speedup vs baseline: 1.1024x; 1.0010x over previous
#include <cuda_runtime.h>
#include <cuda_bf16.h>
#include <cstdint>
#include <cstddef>

#define D_MODEL 1024
#define D_SAE   8192
#define N_MAX   16384
#define KTOP    32
#define NCAND   256
#define CTHRESH 40
#define SUBT    56

// ---------------------------------------------------------------------------
// static device scratch (no runtime allocation)
// ---------------------------------------------------------------------------
static __device__ __nv_bfloat16 g_ah[(size_t)N_MAX * D_MODEL];   // 32 MB  bf16(x - b_dec)
static __device__ __nv_bfloat16 g_wh[(size_t)D_SAE * D_MODEL];   // 16 MB  bf16(W_enc)
static __device__ float g_wdt[(size_t)D_SAE * D_MODEL];          // 32 MB  W_dec^T
static __device__ int   g_cand[(size_t)N_MAX * NCAND];           // 16 MB
static __device__ int   g_nc[N_MAX];
static __device__ int   g_tidx[N_MAX * KTOP];
static __device__ float g_tval[N_MAX * KTOP];
static __device__ float g_mse[N_MAX];
static __device__ float g_l0[N_MAX];

// ---------------------------------------------------------------------------
// helpers
// ---------------------------------------------------------------------------
__device__ __forceinline__ uint32_t s2u(const void* p) {
    uint32_t a;
    asm("{ .reg .u64 t; cvta.to.shared.u64 t, %1; cvt.u32.u64 %0, t; }"
        : "=r"(a) : "l"(p));
    return a;
}
__device__ __forceinline__ void cpa16(uint32_t s, const void* g) {
    asm volatile("cp.async.cg.shared.global [%0], [%1], 16;"
                 :: "r"(s), "l"(g));
}
__device__ __forceinline__ uint32_t pack2(float a, float b) {
    __nv_bfloat162 h = __floats2bfloat162_rn(a, b);
    return *reinterpret_cast<uint32_t*>(&h);
}
__device__ __forceinline__ void ldsm4(uint32_t* r, uint32_t addr) {
    asm volatile("ldmatrix.sync.aligned.m8n8.x4.shared.b16 {%0,%1,%2,%3}, [%4];"
                 : "=r"(r[0]), "=r"(r[1]), "=r"(r[2]), "=r"(r[3]) : "r"(addr));
}
__device__ __forceinline__ void mma16816(float* c, const uint32_t* a,
                                         const uint32_t* b) {
    asm volatile(
        "mma.sync.aligned.m16n8k16.row.col.f32.bf16.bf16.f32 "
        "{%0,%1,%2,%3}, {%4,%5,%6,%7}, {%8,%9}, {%0,%1,%2,%3};"
        : "+f"(c[0]), "+f"(c[1]), "+f"(c[2]), "+f"(c[3])
        : "r"(a[0]), "r"(a[1]), "r"(a[2]), "r"(a[3]), "r"(b[0]), "r"(b[1]));
}
// monotonic orderable key for float
__device__ __forceinline__ uint32_t fkey(float v) {
    uint32_t u = __float_as_uint(v);
    return (u & 0x80000000u) ? ~u : (u | 0x80000000u);
}

// ---------------------------------------------------------------------------
// Kernel A: bf16(x - b_dec)
// ---------------------------------------------------------------------------
__global__ __launch_bounds__(256) void convert_x_kernel(
    const float* __restrict__ x, const float* __restrict__ bdec)
{
    const size_t i = ((size_t)blockIdx.x * 256 + threadIdx.x) * 4;
    float4 v = *(const float4*)(x + i);
    const float4 bd = *(const float4*)(bdec + (i & (D_MODEL - 1)));
    uint2 h;
    h.x = pack2(v.x - bd.x, v.y - bd.y);
    h.y = pack2(v.z - bd.z, v.w - bd.w);
    *(uint2*)(g_ah + i) = h;
}

// Kernel B: bf16(W_enc)
__global__ __launch_bounds__(256) void convert_w_kernel(const float* __restrict__ w)
{
    const size_t i = ((size_t)blockIdx.x * 256 + threadIdx.x) * 4;
    float4 v = *(const float4*)(w + i);
    uint2 h;
    h.x = pack2(v.x, v.y);
    h.y = pack2(v.z, v.w);
    *(uint2*)(g_wh + i) = h;
}

// ---------------------------------------------------------------------------
// Kernel C: approximate encode GEMM via mma.sync bf16 (fp32 accum)
// BM=BN=128, BK=32, 8 warps (4x2), warp tile 32x64, 3-stage cp.async
// pipeline with ONE __syncthreads per K-stage.
// 80-byte smem row stride -> conflict-free ldmatrix.
// ---------------------------------------------------------------------------
#define TILE_B   10240            // 128 rows * 80 bytes
#define OFF_A    0
#define OFF_B    (TILE_B)
#define STAGE_B  (2 * TILE_B)     // 20480
#define NSTAGE   3
#define GEMM_SMEM (NSTAGE * STAGE_B)   // 61440

__global__ __launch_bounds__(256, 2) void enc_gemm_mma(
    const float* __restrict__ benc, float* __restrict__ pre)
{
    extern __shared__ char smbuf[];
    const uint32_t sb = s2u(smbuf);
    const int tid = threadIdx.x, wid = tid >> 5, lane = tid & 31;
    const size_t bm = (size_t)blockIdx.y * 128;
    const size_t bn = (size_t)blockIdx.x * 128;
    const int warpM = (wid & 3) * 32;
    const int warpN = (wid >> 2) * 64;

    const char* gA = (const char*)g_ah + bm * 2048;
    const char* gB = (const char*)g_wh + bn * 2048;

    const int q0r = tid >> 2, q0c = tid & 3;
    const int q1r = (tid + 256) >> 2, q1c = tid & 3;
    const uint32_t so0 = q0r * 80 + q0c * 16;
    const uint32_t so1 = q1r * 80 + q1c * 16;

    auto load_stage = [&](int s, int buf) {
        const uint32_t base = sb + buf * STAGE_B;
        const size_t go0 = (size_t)q0r * 2048 + (size_t)s * 64 + q0c * 16;
        const size_t go1 = (size_t)q1r * 2048 + (size_t)s * 64 + q1c * 16;
        cpa16(base + OFF_A + so0, gA + go0);
        cpa16(base + OFF_A + so1, gA + go1);
        cpa16(base + OFF_B + so0, gB + go0);
        cpa16(base + OFF_B + so1, gB + go1);
    };

    float acc[2][8][4];
    #pragma unroll
    for (int i = 0; i < 2; i++)
        #pragma unroll
        for (int j = 0; j < 8; j++)
            #pragma unroll
            for (int k = 0; k < 4; k++) acc[i][j][k] = 0.f;

    const uint32_t aBase =
        (uint32_t)(warpM + (lane & 15)) * 80 + (uint32_t)(lane >> 4) * 16;
    const uint32_t bBase =
        (uint32_t)(warpN + (lane & 7) + ((lane >> 4) & 1) * 8) * 80 +
        (uint32_t)((lane >> 3) & 1) * 16;

    // prologue: stages 0,1 into buffers 0,1
    load_stage(0, 0);
    asm volatile("cp.async.commit_group;" ::: "memory");
    load_stage(1, 1);
    asm volatile("cp.async.commit_group;" ::: "memory");

    int buf = 0;
    #pragma unroll 1
    for (int s = 0; s < 32; s++) {
        // stage s resident once <=1 group pending (only s+1 outstanding)
        asm volatile("cp.async.wait_group 1;" ::: "memory");
        __syncthreads();   // also guarantees compute of s-1 fully done ->
                           // its buffer is reusable for stage s+2 below
        if (s + 2 < 32) {
            int nb = buf + 2; if (nb >= NSTAGE) nb -= NSTAGE;
            load_stage(s + 2, nb);
            asm volatile("cp.async.commit_group;" ::: "memory");
        } else {
            // keep group counting consistent: commit empty group
            asm volatile("cp.async.commit_group;" ::: "memory");
        }

        const uint32_t base = sb + buf * STAGE_B;
        #pragma unroll
        for (int ks = 0; ks < 2; ks++) {
            const uint32_t kso = ks * 32;
            uint32_t a0[4], a1[4], bb[4][4];
            ldsm4(a0, base + OFF_A + aBase + kso);
            ldsm4(a1, base + OFF_A + aBase + 1280 + kso);
            #pragma unroll
            for (int nt = 0; nt < 4; nt++)
                ldsm4(bb[nt], base + OFF_B + bBase + nt * 1280 + kso);
            #pragma unroll
            for (int ni = 0; ni < 8; ni++) {
                const uint32_t* bf = &bb[ni >> 1][(ni & 1) * 2];
                mma16816(acc[0][ni], a0, bf);
                mma16816(acc[1][ni], a1, bf);
            }
        }
        buf++; if (buf >= NSTAGE) buf = 0;
    }

    // epilogue: + b_enc, write approx pre
    const int gr = lane >> 2;
    const int cp = (lane & 3) * 2;
    #pragma unroll
    for (int mi = 0; mi < 2; mi++) {
        #pragma unroll
        for (int j = 0; j < 2; j++) {
            const size_t row = bm + warpM + mi * 16 + gr + j * 8;
            float* prow = pre + row * D_SAE + bn + warpN;
            const float* be = benc + bn + warpN;
            #pragma unroll
            for (int ni = 0; ni < 8; ni++) {
                const int col = ni * 8 + cp;
                float2 o;
                o.x = acc[mi][ni][j * 2 + 0] + __ldg(be + col);
                o.y = acc[mi][ni][j * 2 + 1] + __ldg(be + col + 1);
                *(float2*)(prow + col) = o;
            }
        }
    }
}

// ---------------------------------------------------------------------------
// Kernel D: W_dec transpose
// ---------------------------------------------------------------------------
__global__ void transpose_wdec_kernel(const float* __restrict__ Wdec)
{
    __shared__ float t[32][33];
    const int bx = blockIdx.x * 32;   // d_sae
    const int by = blockIdx.y * 32;   // d_model
    const int tx = threadIdx.x, ty = threadIdx.y;   // (32, 8)
    #pragma unroll
    for (int i = 0; i < 32; i += 8)
        t[ty + i][tx] = Wdec[(size_t)(by + ty + i) * D_SAE + bx + tx];
    __syncthreads();
    #pragma unroll
    for (int i = 0; i < 32; i += 8)
        g_wdt[(size_t)(bx + ty + i) * D_MODEL + by + tx] = t[tx][ty + i];
}

// ---------------------------------------------------------------------------
// Kernel E: per-row candidate select: coarse 2048-bucket histogram, then
// 64-way sub-bucket refinement inside the threshold bucket so the emitted
// candidate count lands near SUBT (instead of ~136). Then zero feat row.
// ---------------------------------------------------------------------------
__global__ __launch_bounds__(256) void cand_kernel(float* __restrict__ feat)
{
    __shared__ float srow[D_SAE];
    __shared__ unsigned hist[2048];
    __shared__ unsigned csum[256];
    __shared__ unsigned subh[64];
    __shared__ int sT, sTs;
    __shared__ unsigned sAbove;
    __shared__ int scnt;

    const int row = blockIdx.x, tid = threadIdx.x;
    float* f = feat + (size_t)row * D_SAE;

    #pragma unroll
    for (int j = 0; j < 8; j++) hist[tid + j * 256] = 0;
    if (tid < 64) subh[tid] = 0;
    if (tid == 0) scnt = 0;
    __syncthreads();

    for (int i = tid; i < D_SAE / 4; i += 256) {
        float4 v = *(const float4*)&f[i * 4];
        *(float4*)&srow[i * 4] = v;
        atomicAdd(&hist[fkey(v.x) >> 21], 1u);
        atomicAdd(&hist[fkey(v.y) >> 21], 1u);
        atomicAdd(&hist[fkey(v.z) >> 21], 1u);
        atomicAdd(&hist[fkey(v.w) >> 21], 1u);
    }
    __syncthreads();

    // chunk sums (8 buckets/thread) + inclusive suffix scan
    unsigned cs = 0;
    #pragma unroll
    for (int j = 0; j < 8; j++) cs += hist[tid * 8 + j];
    csum[tid] = cs;
    __syncthreads();
    for (int off = 1; off < 256; off <<= 1) {
        unsigned add = (tid + off < 256) ? csum[tid + off] : 0;
        __syncthreads();
        csum[tid] += add;
        __syncthreads();
    }
    // owner of the crossing chunk finds the highest bucket with cum >= CTHRESH
    {
        const unsigned here = csum[tid];
        const unsigned next = (tid < 255) ? csum[tid + 1] : 0;
        if (here >= CTHRESH && next < CTHRESH) {
            unsigned running = next;
            int T = tid * 8;
            for (int b = tid * 8 + 7; b >= tid * 8; b--) {
                running += hist[b];
                if (running >= CTHRESH) { T = b; break; }
            }
            sT = T;
            // count strictly above bucket T
            unsigned abv = next;
            for (int b = tid * 8 + 7; b > T; b--) abv += hist[b];
            sAbove = abv;
        }
    }
    __syncthreads();
    const int T = sT;
    const unsigned above = sAbove;

    // sub-histogram of bucket T members (6 more key bits -> 64 sub-buckets)
    for (int i = tid; i < D_SAE; i += 256) {
        const uint32_t k = fkey(srow[i]);
        if ((int)(k >> 21) == T)
            atomicAdd(&subh[(k >> 15) & 63u], 1u);
    }
    __syncthreads();
    if (tid == 0) {
        unsigned run = above;
        int Ts = 0;
        for (int b = 63; b >= 0; b--) {
            run += subh[b];
            if (run >= SUBT) { Ts = b; break; }
        }
        sTs = Ts;
    }
    __syncthreads();
    const int Ts = sTs;

    // compact candidate indices to global scratch
    for (int i = tid; i < D_SAE; i += 256) {
        const uint32_t k = fkey(srow[i]);
        const int b = (int)(k >> 21);
        if (b > T || (b == T && (int)((k >> 15) & 63u) >= Ts)) {
            int p = atomicAdd(&scnt, 1);
            if (p < NCAND) g_cand[(size_t)row * NCAND + p] = i;
        }
    }
    __syncthreads();
    if (tid == 0) g_nc[row] = scnt < NCAND ? scnt : NCAND;

    // zero feature row (fixup kernel scatters afterwards)
    const float4 z = {0.f, 0.f, 0.f, 0.f};
    for (int i = tid; i < D_SAE / 4; i += 256)
        *(float4*)&f[i * 4] = z;
}

// ---------------------------------------------------------------------------
// Kernel F: exact fp32 recompute of candidates, exact top-32, scatter.
// ---------------------------------------------------------------------------
__global__ __launch_bounds__(256) void fixup_kernel(
    const float* __restrict__ x, const float* __restrict__ Wenc,
    const float* __restrict__ benc, const float* __restrict__ bdec,
    float* __restrict__ feat)
{
    __shared__ float xs[D_MODEL];
    __shared__ float cv[NCAND];
    __shared__ int   ci[NCAND];
    __shared__ float kv[KTOP];
    __shared__ int   kidx[KTOP];

    const int row = blockIdx.x, tid = threadIdx.x;
    const int wid = tid >> 5, lane = tid & 31;
    const int nc = g_nc[row];

    for (int i = tid; i < D_MODEL; i += 256)
        xs[i] = x[(size_t)row * D_MODEL + i] - bdec[i];
    if (tid < nc) ci[tid] = g_cand[(size_t)row * NCAND + tid];
    __syncthreads();

    // exact fp32 dot per candidate (one warp per candidate, round-robin)
    for (int c = wid; c < nc; c += 8) {
        const float* wr = Wenc + (size_t)ci[c] * D_MODEL;
        float acc = 0.f;
        #pragma unroll
        for (int j = 0; j < 8; j++) {
            const int o = (j * 32 + lane) * 4;
            const float4 w = *(const float4*)(wr + o);
            const float4 a = *(const float4*)(xs + o);
            acc += a.x * w.x + a.y * w.y + a.z * w.z + a.w * w.w;
        }
        #pragma unroll
        for (int o = 16; o; o >>= 1)
            acc += __shfl_xor_sync(0xffffffffu, acc, o);
        if (lane == 0) cv[c] = acc + __ldg(benc + ci[c]);
    }
    __syncthreads();

    // warp 0: exact top-32 (value desc, tie -> lower feature index)
    if (wid == 0) {
        for (int t = 0; t < KTOP; t++) {
            float bv = -3.4e38f; int bi = 0x7fffffff, bs = -1;
            for (int s = lane; s < nc; s += 32) {
                const float v = cv[s]; const int idx = ci[s];
                if (v > bv || (v == bv && idx < bi)) { bv = v; bi = idx; bs = s; }
            }
            #pragma unroll
            for (int o = 16; o; o >>= 1) {
                const float ov = __shfl_xor_sync(0xffffffffu, bv, o);
                const int   oi = __shfl_xor_sync(0xffffffffu, bi, o);
                const int   os = __shfl_xor_sync(0xffffffffu, bs, o);
                if (ov > bv || (ov == bv && oi < bi)) { bv = ov; bi = oi; bs = os; }
            }
            if (lane == 0) {
                kv[t] = bv; kidx[t] = bi;
                if (bs >= 0) cv[bs] = -3.4e38f;
            }
            __syncwarp();
        }
        if (lane < KTOP) {
            const int idx = kidx[lane];
            float v = kv[lane]; if (v < 0.f) v = 0.f;
            g_tval[row * KTOP + lane] = v;
            g_tidx[row * KTOP + lane] = idx;
            if (idx != 0x7fffffff)
                feat[(size_t)row * D_SAE + idx] = v;
        }
    }
}

// ---------------------------------------------------------------------------
// Kernel G: sparse decode + per-row partials
// ---------------------------------------------------------------------------
__global__ __launch_bounds__(256) void decode_kernel(
    const float* __restrict__ x, const float* __restrict__ bdec,
    float* __restrict__ xhat)
{
    __shared__ int   si[KTOP];
    __shared__ float sv[KTOP];
    __shared__ float red[256];

    const int row = blockIdx.x, tid = threadIdx.x;
    if (tid < KTOP) {
        si[tid] = g_tidx[row * KTOP + tid];
        sv[tid] = g_tval[row * KTOP + tid];
    }
    __syncthreads();

    float4 acc = *(const float4*)&bdec[tid * 4];
    #pragma unroll 8
    for (int k = 0; k < KTOP; k++) {
        const float v = sv[k];
        const float4 w = *(const float4*)&g_wdt[(size_t)si[k] * D_MODEL + tid * 4];
        acc.x += v * w.x; acc.y += v * w.y; acc.z += v * w.z; acc.w += v * w.w;
    }
    *(float4*)&xhat[(size_t)row * D_MODEL + tid * 4] = acc;

    const float4 xv = *(const float4*)&x[(size_t)row * D_MODEL + tid * 4];
    const float dx = acc.x - xv.x, dy = acc.y - xv.y,
                dz = acc.z - xv.z, dw = acc.w - xv.w;
    red[tid] = dx * dx + dy * dy + dz * dz + dw * dw;
    __syncthreads();
    for (int s = 128; s > 0; s >>= 1) {
        if (tid < s) red[tid] += red[tid + s];
        __syncthreads();
    }
    if (tid == 0) {
        g_mse[row] = red[0];
        int c = 0;
        #pragma unroll
        for (int k = 0; k < KTOP; k++) c += (sv[k] > 0.f);
        g_l0[row] = (float)c;
    }
}

// ---------------------------------------------------------------------------
// Kernel H: final scalars
// ---------------------------------------------------------------------------
__global__ __launch_bounds__(256) void finalize_kernel(
    float* __restrict__ scal, int N, float inv_elems)
{
    __shared__ float r1[256], r2[256];
    const int tid = threadIdx.x;
    float s1 = 0.f, s2 = 0.f;
    for (int i = tid; i < N; i += 256) { s1 += g_mse[i]; s2 += g_l0[i]; }
    r1[tid] = s1; r2[tid] = s2;
    __syncthreads();
    for (int s = 128; s > 0; s >>= 1) {
        if (tid < s) { r1[tid] += r1[tid + s]; r2[tid] += r2[tid + s]; }
        __syncthreads();
    }
    if (tid == 0) {
        const float mse = r1[0] * inv_elems;
        scal[0] = mse;  scal[1] = mse;  scal[2] = 0.f;
        scal[3] = r2[0] / (float)N;
    }
}

// ---------------------------------------------------------------------------
// launch
// ---------------------------------------------------------------------------
extern "C" void kernel_launch(void* const* d_in, const int* in_sizes, int n_in,
                              void* d_out, int out_size)
{
    const float* x    = (const float*)d_in[0];
    const float* Wenc = (const float*)d_in[1];
    const float* benc = (const float*)d_in[2];
    const float* Wdec = (const float*)d_in[3];
    const float* bdec = (const float*)d_in[4];

    const int d_model = in_sizes[4];            // 1024
    const int N       = in_sizes[0] / d_model;  // 16384
    (void)n_in; (void)out_size;

    float* out  = (float*)d_out;
    float* xhat = out;                                   // [N, d_model]
    float* feat = out + (size_t)N * d_model;             // [N, d_sae]
    float* scal = feat + (size_t)N * D_SAE;              // 4 scalars

    // 60 KB dynamic smem for the 3-stage GEMM (idempotent, capture-safe)
    cudaFuncSetAttribute(enc_gemm_mma,
                         cudaFuncAttributeMaxDynamicSharedMemorySize, GEMM_SMEM);

    // 1. bf16 conversions
    convert_x_kernel<<<(N * D_MODEL) / 1024, 256>>>(x, bdec);
    convert_w_kernel<<<(D_SAE * D_MODEL) / 1024, 256>>>(Wenc);

    // 2. W_dec transpose
    transpose_wdec_kernel<<<dim3(D_SAE / 32, D_MODEL / 32), dim3(32, 8)>>>(Wdec);

    // 3. approximate encode GEMM (bf16 tensor cores) -> feat region
    dim3 gg(D_SAE / 128, N / 128);
    enc_gemm_mma<<<gg, 256, GEMM_SMEM>>>(benc, feat);

    // 4. per-row candidate selection (sub-bucket refined) + zero feat
    cand_kernel<<<N, 256>>>(feat);

    // 5. exact fp32 fixup: recompute candidates, exact top-32, scatter
    fixup_kernel<<<N, 256>>>(x, Wenc, benc, bdec, feat);

    // 6. sparse decode + per-row partials
    decode_kernel<<<N, 256>>>(x, bdec, xhat);

    // 7. scalars
    finalize_kernel<<<1, 256>>>(scal, N, 1.0f / ((float)N * (float)d_model));
}